// round 8
// baseline (speedup 1.0000x reference)
#include <cuda_runtime.h>
#include <cstdint>

#define N_   32
#define C_   256
#define O_   256
#define HW_  56
#define PIX  3136
#define CNTS 802816.0f
#define EPSF 1e-5f

// ---------------- device scratch ----------------
__device__ float    g_asum[N_];
__device__ float    g_m[O_];
__device__ __align__(16) unsigned g_wt[9 * 8 * O_];       // [tap][w8][o]
__device__ int      g_pw[O_ * 9];                          // popc per (o,tap)
__device__ __align__(16) unsigned g_xbits[(size_t)N_ * PIX * 8]; // [n][pix][word]
__device__ int      g_xz_count;
__device__ int      g_wz_count;
__device__ int      g_xz_list[4096];
__device__ int      g_wz_list[64];

__device__ __forceinline__ float alpha_of(int n) {
    return fmaxf(2.f * g_asum[n] / CNTS, EPSF);
}

// ---------------- K0 ----------------
__global__ void k_zero() {
    int t = blockIdx.x * blockDim.x + threadIdx.x;
    if (t < N_) g_asum[t] = 0.f;
    if (t < O_ * 9) g_pw[t] = 0;
    if (t == 0) { g_xz_count = 0; g_wz_count = 0; }
}

// ---------------- K1: pack x ----------------
__global__ void k_packx(const float* __restrict__ x) {
    int b   = blockIdx.x;
    int n   = b & 31;
    int pix = (b >> 5) * 256 + threadIdx.x;
    int tid = threadIdx.x;

    unsigned bits[8] = {0,0,0,0,0,0,0,0};
    float s0 = 0.f, s1 = 0.f, s2 = 0.f, s3 = 0.f;

    if (pix < PIX) {
        const float* base = x + (size_t)n * C_ * PIX + pix;
#pragma unroll
        for (int w8 = 0; w8 < 8; w8++) {
            unsigned bb = 0;
#pragma unroll
            for (int c2 = 0; c2 < 32; c2++) {
                float v = base[(size_t)(w8 * 32 + c2) * PIX];
                float a = fabsf(v);
                if ((c2 & 3) == 0) s0 += a; else if ((c2 & 3) == 1) s1 += a;
                else if ((c2 & 3) == 2) s2 += a; else s3 += a;
                bb |= ((unsigned)(v < 0.f)) << c2;
                if (v == 0.f) {
                    int idx = atomicAdd(&g_xz_count, 1);
                    if (idx < 4096) g_xz_list[idx] = (n * C_ + w8 * 32 + c2) * PIX + pix;
                }
            }
            bits[w8] = bb;
        }
        uint4* dst = (uint4*)&g_xbits[((size_t)n * PIX + pix) * 8];
        dst[0] = make_uint4(bits[0], bits[1], bits[2], bits[3]);
        dst[1] = make_uint4(bits[4], bits[5], bits[6], bits[7]);
    }

    __shared__ float red[256];
    red[tid] = (s0 + s1) + (s2 + s3);
    __syncthreads();
    for (int st = 128; st > 0; st >>= 1) {
        if (tid < st) red[tid] += red[tid + st];
        __syncthreads();
    }
    if (tid == 0) atomicAdd(&g_asum[n], red[0]);
}

// ---------------- K2: pack w  ([tap][w8][o] layout) ----------------
__global__ void k_packw(const float* __restrict__ w) {
    int o = blockIdx.x;
    int tid = threadIdx.x;
    int j = tid >> 5, lane = tid & 31;
    int c = j * 32 + lane;

    float s = 0.f;
#pragma unroll
    for (int tap = 0; tap < 9; tap++) {
        float v = w[((size_t)(o * C_ + c)) * 9 + tap];
        s += fabsf(v);
        unsigned bal = __ballot_sync(0xffffffffu, v < 0.f);
        if (lane == 0) {
            g_wt[(tap * 8 + j) * O_ + o] = bal;
            atomicAdd(&g_pw[o * 9 + tap], __popc(bal));
        }
        if (v == 0.f) {
            int idx = atomicAdd(&g_wz_count, 1);
            if (idx < 64) g_wz_list[idx] = (o * C_ + c) * 9 + tap;
        }
    }
    __shared__ float red[256];
    red[tid] = s;
    __syncthreads();
    for (int st = 128; st > 0; st >>= 1) {
        if (tid < st) red[tid] += red[tid + st];
        __syncthreads();
    }
    if (tid == 0) g_m[o] = red[0] / 2304.f;
}

// ---------------- K3: XNOR-popcount conv, 4px x 4o register tile ----------------
// grid = 32 n * 4 rowgroups(16 rows) * 4 o-groups(64 o) = 512 blocks, 224 thr
// thread: row16 = tid%16, c14 = tid/16, ow0 = 4*c14. 4 horizontal px, 4 o at a time.
// SMEM x tile: [word(8)][row(18)][col(68)] ; row stride 272B = 17*16B -> conflict-free LDS.128
#define XT_RS   68
#define XT_PS   (18 * 68)

__global__ __launch_bounds__(224, 4) void k_conv(float* __restrict__ out) {
    __shared__ __align__(16) unsigned xt[8 * XT_PS];

    int b = blockIdx.x;
    int n = b & 31;
    int rowBase = ((b >> 5) & 3) * 16;
    int oBase   = (b >> 7) * 64;
    int tid = threadIdx.x;

    // zero tile (halo / invalid rows stay zero)
    uint4 z4 = make_uint4(0u, 0u, 0u, 0u);
    for (int i = tid; i < 8 * XT_PS / 4; i += 224) ((uint4*)xt)[i] = z4;
    __syncthreads();

    // fill: tile row r <-> ih = rowBase-1+r ; col ci <-> iw = ci-1, stored at cidx=ci+3
    for (int idx = tid; idx < 18 * 58; idx += 224) {
        int r = idx / 58, ci = idx % 58;
        int ih = rowBase - 1 + r, iw = ci - 1;
        if (ih >= 0 && ih < HW_ && iw >= 0 && iw < HW_) {
            const uint4* src = (const uint4*)&g_xbits[((size_t)n * PIX + ih * HW_ + iw) * 8];
            uint4 a = src[0], bq = src[1];
            unsigned* d = &xt[r * XT_RS + ci + 3];
            d[0 * XT_PS] = a.x;  d[1 * XT_PS] = a.y;
            d[2 * XT_PS] = a.z;  d[3 * XT_PS] = a.w;
            d[4 * XT_PS] = bq.x; d[5 * XT_PS] = bq.y;
            d[6 * XT_PS] = bq.z; d[7 * XT_PS] = bq.w;
        }
    }
    __syncthreads();

    int row16 = tid & 15;
    int ow0 = (tid >> 4) * 4;
    int oh = rowBase + row16;
    bool ohValid = (oh < HW_);

    // per-pixel invalid-tap masks (padding)
    unsigned bmv[4];
#pragma unroll
    for (int p = 0; p < 4; p++) {
        int ow = ow0 + p;
        unsigned bm = 0;
#pragma unroll
        for (int t = 0; t < 9; t++) {
            int kh = t / 3, kw = t % 3;
            bool inv = (kh == 0 && oh == 0) || (kh == 2 && oh == HW_ - 1) ||
                       (kw == 0 && ow == 0) || (kw == 2 && ow == HW_ - 1);
            if (inv) bm |= 1u << t;
        }
        bmv[p] = bm;
    }

    float al = alpha_of(n);

    for (int og = 0; og < 16; og++) {
        int o0 = oBase + og * 4;
        int acc[16];
#pragma unroll
        for (int i = 0; i < 16; i++) acc[i] = 0;

#pragma unroll 1
        for (int kh = 0; kh < 3; kh++) {
            const unsigned* rb = &xt[(row16 + kh) * XT_RS + ow0];
#pragma unroll
            for (int w8 = 0; w8 < 8; w8++) {
                const unsigned* xp = rb + w8 * XT_PS;
                uint4 xa = *(const uint4*)(xp);
                uint4 xb = *(const uint4*)(xp + 4);
                uint4 xc = *(const uint4*)(xp + 8);
                unsigned xw[12] = {xa.x, xa.y, xa.z, xa.w,
                                   xb.x, xb.y, xb.z, xb.w,
                                   xc.x, xc.y, xc.z, xc.w};
#pragma unroll
                for (int kw = 0; kw < 3; kw++) {
                    uint4 wv = __ldg((const uint4*)&g_wt[((kh * 3 + kw) * 8 + w8) * O_ + o0]);
#pragma unroll
                    for (int p = 0; p < 4; p++) {
                        unsigned xv = xw[3 + p + kw];
                        acc[p * 4 + 0] += __popc(xv ^ wv.x);
                        acc[p * 4 + 1] += __popc(xv ^ wv.y);
                        acc[p * 4 + 2] += __popc(xv ^ wv.z);
                        acc[p * 4 + 3] += __popc(xv ^ wv.w);
                    }
                }
            }
        }

#pragma unroll
        for (int o = 0; o < 4; o++) {
            float f = al * __ldg(&g_m[o0 + o]);
            float4 v;
#pragma unroll
            for (int p = 0; p < 4; p++) {
                int S = 2304 - 2 * acc[p * 4 + o];
                unsigned m2 = bmv[p];
                while (m2) {
                    int t = __ffs(m2) - 1;
                    m2 &= m2 - 1;
                    S -= 256 - 2 * __ldg(&g_pw[(o0 + o) * 9 + t]);
                }
                (&v.x)[p] = f * (float)S;
            }
            if (ohValid)
                *(float4*)&out[((size_t)(n * O_ + o0 + o)) * PIX + oh * HW_ + ow0] = v;
        }
    }
}

// ---------------- K4: exact correction for x==0 ----------------
__global__ void k_xzero(float* __restrict__ out) {
    int zc = g_xz_count;
    if (zc > 4096) zc = 4096;
    long total = (long)zc * 2304;
    for (long i = (long)blockIdx.x * blockDim.x + threadIdx.x; i < total;
         i += (long)gridDim.x * blockDim.x) {
        int z = (int)(i / 2304);
        int q = (int)(i % 2304);
        int o = q / 9, tap = q % 9;
        int li = g_xz_list[z];
        int pix = li % PIX;
        int ch = (li / PIX) & 255;
        int n = li / (PIX * C_);
        int h = pix / HW_, wv = pix % HW_;
        int kh = tap / 3, kw = tap % 3;
        int oh = h + 1 - kh, ow = wv + 1 - kw;
        if ((unsigned)oh < HW_ && (unsigned)ow < HW_) {
            unsigned bit = (g_wt[(tap * 8 + (ch >> 5)) * O_ + o] >> (ch & 31)) & 1u;
            float bw = bit ? -1.f : 1.f;
            atomicAdd(&out[((size_t)(n * O_ + o)) * PIX + oh * HW_ + ow],
                      -bw * alpha_of(n) * g_m[o]);
        }
    }
}

// ---------------- K5: exact correction for w==0 ----------------
__global__ void k_wzero(const float* __restrict__ x, float* __restrict__ out) {
    int zc = g_wz_count;
    if (zc > 64) zc = 64;
    long total = (long)zc * N_ * PIX;
    for (long i = (long)blockIdx.x * blockDim.x + threadIdx.x; i < total;
         i += (long)gridDim.x * blockDim.x) {
        int z = (int)(i / ((long)N_ * PIX));
        int rte = (int)(i % ((long)N_ * PIX));
        int n = rte / PIX, pix = rte % PIX;
        int oh = pix / HW_, ow = pix % HW_;
        int li = g_wz_list[z];
        int tap = li % 9;
        int ch = (li / 9) & 255;
        int o = li / (9 * C_);
        int kh = tap / 3, kw = tap % 3;
        int ih = oh - 1 + kh, iw = ow - 1 + kw;
        if ((unsigned)ih < HW_ && (unsigned)iw < HW_) {
            float xv = x[((size_t)(n * C_ + ch)) * PIX + ih * HW_ + iw];
            if (xv != 0.f) {
                float bx = (xv < 0.f) ? -1.f : 1.f;
                atomicAdd(&out[((size_t)(n * O_ + o)) * PIX + pix],
                          -bx * alpha_of(n) * g_m[o]);
            }
        }
    }
}

// ---------------- launch ----------------
extern "C" void kernel_launch(void* const* d_in, const int* in_sizes, int n_in,
                              void* d_out, int out_size) {
    const float* x = (const float*)d_in[0];
    const float* w = (const float*)d_in[1];
    float* out = (float*)d_out;

    k_zero<<<9, 256>>>();
    k_packx<<<416, 256>>>(x);
    k_packw<<<256, 256>>>(w);
    k_conv<<<512, 224>>>(out);
    k_xzero<<<64, 256>>>(out);
    k_wzero<<<128, 256>>>(x, out);
}